// round 12
// baseline (speedup 1.0000x reference)
#include <cuda_runtime.h>
#include <cuda_fp16.h>
#include <cstdint>
#include <cstddef>

#define CHANS 256
#define HWSZ  3136
#define BATCH 32
#define NPOS  (BATCH*HWSZ)        // 100352
#define STEPS 10
#define SCOPE 15
#define PADC  7

#define TILE_P 128                // positions per tile
#define KC     128                // cin per chunk
#define NCHUNK (CHANS/KC)         // 2
#define NTILES (NPOS/TILE_P)      // 784
#define NSM    148                // persistent grid

// fp16 rows, strides in 4B words %32==4 -> ldmatrix 8-row tiles conflict-free
#define RSXW   68                 // X row: 128 pos fp16 = 64 words + 4 pad
#define RSWW   132                // W row: 256 cout fp16 = 128 words + 4 pad
#define XBUFW  (KC*RSXW)          // 8704 words per X buffer (128 k-rows)
#define WRESW  (256*RSWW)         // 33792 words resident W
#define XBUF_BYTES (XBUFW*4)      // 34816
#define SMEM_BYTES ((2*XBUFW + WRESW)*4)   // 204800 B (< 227KB)

// W_eff = sum_{k=0..10} T^k, fp16: g_wh[cin][cout]
__device__ __half g_wh[CHANS*CHANS];

// ---------------- helpers ----------------
__device__ __forceinline__ uint32_t smem_u32(const void* p){
    uint32_t a;
    asm("{ .reg .u64 t; cvta.to.shared.u64 t, %1; cvt.u32.u64 %0, t; }" : "=r"(a) : "l"(p));
    return a;
}
__device__ __forceinline__ uint32_t pkh2(float hi, float lo){
    uint32_t r; asm("cvt.rn.f16x2.f32 %0, %1, %2;" : "=r"(r) : "f"(hi), "f"(lo)); return r;
}
__device__ __forceinline__ void ldmx4t(uint32_t* r, uint32_t addr){
    asm volatile("ldmatrix.sync.aligned.m8n8.x4.trans.shared.b16 {%0,%1,%2,%3}, [%4];"
        : "=r"(r[0]), "=r"(r[1]), "=r"(r[2]), "=r"(r[3]) : "r"(addr));
}
__device__ __forceinline__ void mma16(float* d, const uint32_t* a, uint32_t b0, uint32_t b1){
    asm volatile("mma.sync.aligned.m16n8k16.row.col.f32.f16.f16.f32 "
        "{%0,%1,%2,%3}, {%4,%5,%6,%7}, {%8,%9}, {%0,%1,%2,%3};"
        : "+f"(d[0]), "+f"(d[1]), "+f"(d[2]), "+f"(d[3])
        : "r"(a[0]), "r"(a[1]), "r"(a[2]), "r"(a[3]), "r"(b0), "r"(b1));
}

// ---------------- Kernel 1: build W_eff (fp16) ----------------
// Block j: column j of S = sum_{k=0..STEPS} T^k via S_{s+1} = I + T*S_s (exact,
// includes zero-pad boundaries). Thread i holds S[i][j] = W[cout=i][cin=j];
// writes g_wh[cin=j][cout=i].
__global__ void build_weff_kernel(const float* __restrict__ w){
    __shared__ float sv[CHANS + 2*PADC];
    const int i = threadIdx.x, j = blockIdx.x;
    if (i < PADC){ sv[i] = 0.f; sv[CHANS + PADC + i] = 0.f; }
    float wv[SCOPE];
#pragma unroll
    for (int k = 0; k < SCOPE; ++k) wv[k] = w[k];
    float v = (i == j) ? 1.f : 0.f;
    for (int s = 0; s < STEPS; ++s){
        __syncthreads();
        sv[PADC + i] = v;
        __syncthreads();
        float acc = (i == j) ? 1.f : 0.f;
#pragma unroll
        for (int k = 0; k < SCOPE; ++k) acc = fmaf(wv[k], sv[i + k], acc);
        v = acc;
    }
    g_wh[j * CHANS + i] = __float2half_rn(v);
}

// ---------------- Kernel 2: persistent GEMM out = W_eff * X ----------------
// 148 persistent CTAs, 512 threads. Operands in SMEM as plain fp16 [k][col];
// fragments via ldmatrix.x4.trans. W fully resident. X double-buffered in
// KC=128 chunks (2 per tile, 2 barriers per tile); next chunk staged in two
// halves: LDG h0 @top -> STS h0 + LDG h1 @mid -> STS h1 @bottom, so each LDG
// has >= half a chunk (~1300 cyc) of compute cover.
__global__ void __launch_bounds__(512, 1)
gemm_kernel(const float* __restrict__ x, float* __restrict__ out){
    extern __shared__ uint32_t smu[];
    uint32_t* xbuf = smu;              // 2 x [128][RSXW]
    uint32_t* wres = smu + 2*XBUFW;    // [256][RSWW]

    const int tid  = threadIdx.x;
    const int lane = tid & 31;
    const int wid  = tid >> 5;
    const int g = lane >> 2, q = lane & 3;
    const int wp = wid >> 2, wc = wid & 3;
    const int bid = blockIdx.x;

    // ---- one-time W load: plain copy g_wh rows -> [k][cout] fp16 ----
#pragma unroll
    for (int i = 0; i < 16; ++i){
        int id  = tid + i * 512;           // 0..8191
        int row = id >> 5;                 // 0..255 (cin)
        int c8  = (id & 31) << 3;          // cout group of 8
        const uint4 v = *(const uint4*)(g_wh + (size_t)row * CHANS + c8);
        *(uint4*)(wres + row * RSWW + (c8 >> 1)) = v;
    }

    const int ntiles = (NTILES - bid + NSM - 1) / NSM;   // 5 or 6
    const int gend   = ntiles * NCHUNK;                  // 10 or 12

    // X staging: thread -> (k rows sk+{0,32} of a 64-row half; 8 consecutive pos)
    const int sk  = tid >> 4;              // 0..31
    const int sp8 = (tid & 15) << 3;       // 0..120  (8|3136 -> no batch straddle)

    float4 xf[4];
    // half h (0/1) of chunk gc: k rows [gc&1]*128 + h*64 + {sk, sk+32}
    auto ldg_half = [&](int gc, int h){
        int t = gc >> 1, c = gc & 1;
        int tile = bid + t * NSM;
        int sn = tile * TILE_P + sp8;
        int b = sn / HWSZ, p = sn - b * HWSZ;
        const float* s = x + ((size_t)b * CHANS + (size_t)(c * KC + h * 64 + sk)) * HWSZ + p;
        xf[0] = *(const float4*)s;
        xf[1] = *(const float4*)(s + 4);
        xf[2] = *(const float4*)(s + 32 * HWSZ);
        xf[3] = *(const float4*)(s + 32 * HWSZ + 4);
    };
    auto sts_half = [&](uint32_t* buf, int h){
        uint4 v0, v1;
        v0.x = pkh2(xf[0].y, xf[0].x);  v0.y = pkh2(xf[0].w, xf[0].z);
        v0.z = pkh2(xf[1].y, xf[1].x);  v0.w = pkh2(xf[1].w, xf[1].z);
        v1.x = pkh2(xf[2].y, xf[2].x);  v1.y = pkh2(xf[2].w, xf[2].z);
        v1.z = pkh2(xf[3].y, xf[3].x);  v1.w = pkh2(xf[3].w, xf[3].z);
        *(uint4*)(buf + (h * 64 + sk) * RSXW + (sp8 >> 1))      = v0;
        *(uint4*)(buf + (h * 64 + sk + 32) * RSXW + (sp8 >> 1)) = v1;
    };

    // ldmatrix per-lane base addresses (bytes)
    const int a_k = (lane & 7) + ((lane >> 4) << 3);        // A: lanes 16-31 -> +8 k
    const int a_p = ((lane >> 3) & 1) << 3;                 // A: lanes 8-15,24-31 -> +8 pos
    const uint32_t xaddr0 = smem_u32(xbuf) + (uint32_t)(a_k * (RSXW*4) + (wp * 32 + a_p) * 2);
    const int b_k = (lane & 7) + (((lane >> 3) & 1) << 3);  // B: lanes 8-15,24-31 -> +8 k
    const int b_c = ((lane >> 4) << 3);                     // B: lanes 16-31 -> +8 cout
    const uint32_t waddr0 = smem_u32(wres) + (uint32_t)(b_k * (RSWW*4) + (wc * 64 + b_c) * 2);

    float acc[2][8][4];
#pragma unroll
    for (int mt = 0; mt < 2; ++mt)
#pragma unroll
        for (int nt = 0; nt < 8; ++nt)
#pragma unroll
            for (int r = 0; r < 4; ++r) acc[mt][nt][r] = 0.f;

    // prologue: chunk0 into smem
    ldg_half(0, 0); sts_half(xbuf, 0);
    ldg_half(0, 1); sts_half(xbuf, 1);
    __syncthreads();   // covers resident W + buf0

    for (int gc = 0; gc < gend; ++gc){
        const bool more = (gc + 1 < gend);
        uint32_t* nbuf = xbuf + ((gc + 1) & 1) * XBUFW;
        if (more) ldg_half(gc + 1, 0);

        const uint32_t xa_c = xaddr0 + (uint32_t)((gc & 1) * XBUF_BYTES);
        const uint32_t wa_c = waddr0 + (uint32_t)((gc & 1) * KC * (RSWW*4));

        // first half: k16 steps 0..3
#pragma unroll
        for (int ks = 0; ks < 4; ++ks){
            const uint32_t xa_k = xa_c + (uint32_t)(ks * 16 * (RSXW*4));
            const uint32_t wa_k = wa_c + (uint32_t)(ks * 16 * (RSWW*4));
            uint32_t a[2][4];
            ldmx4t(a[0], xa_k);
            ldmx4t(a[1], xa_k + 32);
#pragma unroll
            for (int j = 0; j < 4; ++j){
                uint32_t b[4];
                ldmx4t(b, wa_k + (uint32_t)(j * 32));
                mma16(acc[0][2*j],   a[0], b[0], b[1]);
                mma16(acc[1][2*j],   a[1], b[0], b[1]);
                mma16(acc[0][2*j+1], a[0], b[2], b[3]);
                mma16(acc[1][2*j+1], a[1], b[2], b[3]);
            }
        }

        if (more){
            sts_half(nbuf, 0);       // h0 LDG had ~half a chunk of cover
            ldg_half(gc + 1, 1);     // h1 covered by second half
        }

        // second half: k16 steps 4..7
#pragma unroll
        for (int ks = 4; ks < 8; ++ks){
            const uint32_t xa_k = xa_c + (uint32_t)(ks * 16 * (RSXW*4));
            const uint32_t wa_k = wa_c + (uint32_t)(ks * 16 * (RSWW*4));
            uint32_t a[2][4];
            ldmx4t(a[0], xa_k);
            ldmx4t(a[1], xa_k + 32);
#pragma unroll
            for (int j = 0; j < 4; ++j){
                uint32_t b[4];
                ldmx4t(b, wa_k + (uint32_t)(j * 32));
                mma16(acc[0][2*j],   a[0], b[0], b[1]);
                mma16(acc[1][2*j],   a[1], b[0], b[1]);
                mma16(acc[0][2*j+1], a[0], b[2], b[3]);
                mma16(acc[1][2*j+1], a[1], b[2], b[3]);
            }
        }

        if (more) sts_half(nbuf, 1);

        // per-tile epilogue (overlaps STS completion / barrier)
        if ((gc & 1) == 1){
            int tile = bid + (gc >> 1) * NSM;
#pragma unroll
            for (int mt = 0; mt < 2; ++mt){
#pragma unroll
                for (int rs = 0; rs < 2; ++rs){
                    int pos = tile * TILE_P + wp * 32 + mt * 16 + g + rs * 8;
                    int b = pos / HWSZ, p = pos - b * HWSZ;
                    float* ob = out + ((size_t)b * CHANS + (size_t)(wc * 64 + 2 * q)) * HWSZ + p;
#pragma unroll
                    for (int nt = 0; nt < 8; ++nt){
                        ob[(size_t)(nt * 8) * HWSZ]     = acc[mt][nt][rs * 2 + 0];
                        ob[(size_t)(nt * 8 + 1) * HWSZ] = acc[mt][nt][rs * 2 + 1];
                    }
                }
            }
#pragma unroll
            for (int mt = 0; mt < 2; ++mt)
#pragma unroll
                for (int nt = 0; nt < 8; ++nt)
#pragma unroll
                    for (int r = 0; r < 4; ++r) acc[mt][nt][r] = 0.f;
        }

        if (more) __syncthreads();
    }
}

// ---------------- launch ----------------
extern "C" void kernel_launch(void* const* d_in, const int* in_sizes, int n_in,
                              void* d_out, int out_size)
{
    const float* acts = (const float*)d_in[0];
    const float* wrec = (const float*)d_in[1];
    float* out        = (float*)d_out;
    (void)in_sizes; (void)n_in; (void)out_size;

    cudaFuncSetAttribute(gemm_kernel, cudaFuncAttributeMaxDynamicSharedMemorySize, SMEM_BYTES);

    build_weff_kernel<<<CHANS, CHANS>>>(wrec);
    gemm_kernel<<<NSM, 512, SMEM_BYTES>>>(acts, out);
}

// round 13
// speedup vs baseline: 1.0771x; 1.0771x over previous
#include <cuda_runtime.h>
#include <cuda_fp16.h>
#include <cstdint>
#include <cstddef>

#define CHANS 256
#define HWSZ  3136
#define BATCH 32
#define NPOS  (BATCH*HWSZ)        // 100352
#define STEPS 10
#define SCOPE 15
#define PADC  7

#define TILE_P 128                // positions per tile
#define KC     64                 // cin per chunk
#define NCHUNK (CHANS/KC)         // 4
#define NTILES (NPOS/TILE_P)      // 784
#define NSM    148                // persistent grid

// fp16 rows, strides in 4B words %32==4 -> ldmatrix 8-row tiles conflict-free
#define RSXW   68                 // X row: 128 pos fp16 = 64 words + 4 pad
#define RSWW   132                // W row: 256 cout fp16 = 128 words + 4 pad
#define XBUFW  (KC*RSXW)          // 4352 words per X buffer (64 k-rows)
#define WRESW  (256*RSWW)         // 33792 words resident W
#define XBUF_BYTES (XBUFW*4)      // 17408
#define SMEM_BYTES ((4*XBUFW + WRESW)*4)   // 204800 B (< 227KB)

// W_eff = sum_{k=0..10} T^k, fp16: g_wh[cin][cout]
__device__ __half g_wh[CHANS*CHANS];

// ---------------- helpers ----------------
__device__ __forceinline__ uint32_t smem_u32(const void* p){
    uint32_t a;
    asm("{ .reg .u64 t; cvta.to.shared.u64 t, %1; cvt.u32.u64 %0, t; }" : "=r"(a) : "l"(p));
    return a;
}
__device__ __forceinline__ uint32_t pkh2(float hi, float lo){
    uint32_t r; asm("cvt.rn.f16x2.f32 %0, %1, %2;" : "=r"(r) : "f"(hi), "f"(lo)); return r;
}
__device__ __forceinline__ void ldmx4t(uint32_t* r, uint32_t addr){
    asm volatile("ldmatrix.sync.aligned.m8n8.x4.trans.shared.b16 {%0,%1,%2,%3}, [%4];"
        : "=r"(r[0]), "=r"(r[1]), "=r"(r[2]), "=r"(r[3]) : "r"(addr));
}
__device__ __forceinline__ void mma16(float* d, const uint32_t* a, uint32_t b0, uint32_t b1){
    asm volatile("mma.sync.aligned.m16n8k16.row.col.f32.f16.f16.f32 "
        "{%0,%1,%2,%3}, {%4,%5,%6,%7}, {%8,%9}, {%0,%1,%2,%3};"
        : "+f"(d[0]), "+f"(d[1]), "+f"(d[2]), "+f"(d[3])
        : "r"(a[0]), "r"(a[1]), "r"(a[2]), "r"(a[3]), "r"(b0), "r"(b1));
}

// ---------------- Kernel 1: build W_eff (fp16) ----------------
// Block j: column j of S = sum_{k=0..STEPS} T^k via S_{s+1} = I + T*S_s (exact,
// includes zero-pad boundaries). Thread i holds S[i][j] = W[cout=i][cin=j];
// writes g_wh[cin=j][cout=i].
__global__ void build_weff_kernel(const float* __restrict__ w){
    __shared__ float sv[CHANS + 2*PADC];
    const int i = threadIdx.x, j = blockIdx.x;
    if (i < PADC){ sv[i] = 0.f; sv[CHANS + PADC + i] = 0.f; }
    float wv[SCOPE];
#pragma unroll
    for (int k = 0; k < SCOPE; ++k) wv[k] = w[k];
    float v = (i == j) ? 1.f : 0.f;
    for (int s = 0; s < STEPS; ++s){
        __syncthreads();
        sv[PADC + i] = v;
        __syncthreads();
        float acc = (i == j) ? 1.f : 0.f;
#pragma unroll
        for (int k = 0; k < SCOPE; ++k) acc = fmaf(wv[k], sv[i + k], acc);
        v = acc;
    }
    g_wh[j * CHANS + i] = __float2half_rn(v);
}

// ---------------- Kernel 2: persistent GEMM out = W_eff * X ----------------
// 148 persistent CTAs, 512 threads. Operands in SMEM as plain fp16 [k][col];
// fragments via ldmatrix.x4.trans. W fully resident. X in a 4-buffer ring of
// KC=64 chunks: at iteration gc, LDG chunk gc+2 at top (full chunk of cover),
// STS it at bottom; barrier only after odd chunks (2 per tile).
// RAW: chunk gc STS'd at gc-2; one of {end gc-2, end gc-1} is odd -> barrier.
// WAR: buffer (gc+2)&3 last read at gc-2; same barrier argument.
__global__ void __launch_bounds__(512, 1)
gemm_kernel(const float* __restrict__ x, float* __restrict__ out){
    extern __shared__ uint32_t smu[];
    uint32_t* xbuf = smu;              // 4 x [64][RSXW]
    uint32_t* wres = smu + 4*XBUFW;    // [256][RSWW]

    const int tid  = threadIdx.x;
    const int lane = tid & 31;
    const int wid  = tid >> 5;
    const int g = lane >> 2, q = lane & 3;
    const int wp = wid >> 2, wc = wid & 3;
    const int bid = blockIdx.x;

    // ---- one-time W load: plain copy g_wh rows -> [k][cout] fp16 ----
#pragma unroll
    for (int i = 0; i < 16; ++i){
        int id  = tid + i * 512;           // 0..8191
        int row = id >> 5;                 // 0..255 (cin)
        int c8  = (id & 31) << 3;          // cout group of 8
        const uint4 v = *(const uint4*)(g_wh + (size_t)row * CHANS + c8);
        *(uint4*)(wres + row * RSWW + (c8 >> 1)) = v;
    }

    const int ntiles = (NTILES - bid + NSM - 1) / NSM;   // 5 or 6
    const int gend   = ntiles * NCHUNK;                  // 20 or 24

    // X staging: thread -> (k rows sk, sk+32; 8 consecutive pos); 8|3136 -> no straddle
    const int sk  = tid >> 4;              // 0..31
    const int sp8 = (tid & 15) << 3;       // 0..120

    float4 xf[4];
    auto ldg_x = [&](int gc){
        int t = gc >> 2, c = gc & 3;
        int tile = bid + t * NSM;
        int sn = tile * TILE_P + sp8;
        int b = sn / HWSZ, p = sn - b * HWSZ;
        const float* s = x + ((size_t)b * CHANS + (size_t)(c * KC + sk)) * HWSZ + p;
        xf[0] = *(const float4*)s;
        xf[1] = *(const float4*)(s + 4);
        xf[2] = *(const float4*)(s + 32 * HWSZ);
        xf[3] = *(const float4*)(s + 32 * HWSZ + 4);
    };
    auto sts_x = [&](uint32_t* buf){
        uint4 v0, v1;
        v0.x = pkh2(xf[0].y, xf[0].x);  v0.y = pkh2(xf[0].w, xf[0].z);
        v0.z = pkh2(xf[1].y, xf[1].x);  v0.w = pkh2(xf[1].w, xf[1].z);
        v1.x = pkh2(xf[2].y, xf[2].x);  v1.y = pkh2(xf[2].w, xf[2].z);
        v1.z = pkh2(xf[3].y, xf[3].x);  v1.w = pkh2(xf[3].w, xf[3].z);
        *(uint4*)(buf + sk * RSXW + (sp8 >> 1))        = v0;
        *(uint4*)(buf + (sk + 32) * RSXW + (sp8 >> 1)) = v1;
    };

    // ldmatrix per-lane base addresses (bytes)
    const int a_k = (lane & 7) + ((lane >> 4) << 3);        // A: lanes 16-31 -> +8 k
    const int a_p = ((lane >> 3) & 1) << 3;                 // A: lanes 8-15,24-31 -> +8 pos
    const uint32_t xaddr0 = smem_u32(xbuf) + (uint32_t)(a_k * (RSXW*4) + (wp * 32 + a_p) * 2);
    const int b_k = (lane & 7) + (((lane >> 3) & 1) << 3);  // B: lanes 8-15,24-31 -> +8 k
    const int b_c = ((lane >> 4) << 3);                     // B: lanes 16-31 -> +8 cout
    const uint32_t waddr0 = smem_u32(wres) + (uint32_t)(b_k * (RSWW*4) + (wc * 64 + b_c) * 2);

    float acc[2][8][4];
#pragma unroll
    for (int mt = 0; mt < 2; ++mt)
#pragma unroll
        for (int nt = 0; nt < 8; ++nt)
#pragma unroll
            for (int r = 0; r < 4; ++r) acc[mt][nt][r] = 0.f;

    // prologue: chunks 0 and 1 into ring buffers 0,1
    ldg_x(0); sts_x(xbuf);
    ldg_x(1); sts_x(xbuf + XBUFW);
    __syncthreads();   // covers resident W + buf0/1

    for (int gc = 0; gc < gend; ++gc){
        const bool stage = (gc + 2 < gend);
        if (stage) ldg_x(gc + 2);          // full chunk of cover before its STS

        const uint32_t xa_c = xaddr0 + (uint32_t)((gc & 3) * XBUF_BYTES);
        const uint32_t wa_c = waddr0 + (uint32_t)((gc & 3) * KC * (RSWW*4));
#pragma unroll
        for (int ks = 0; ks < 4; ++ks){
            const uint32_t xa_k = xa_c + (uint32_t)(ks * 16 * (RSXW*4));
            const uint32_t wa_k = wa_c + (uint32_t)(ks * 16 * (RSWW*4));
            uint32_t a[2][4];
            ldmx4t(a[0], xa_k);            // pos wp*32 + 0..15
            ldmx4t(a[1], xa_k + 32);       // pos +16
#pragma unroll
            for (int j = 0; j < 4; ++j){
                uint32_t b[4];
                ldmx4t(b, wa_k + (uint32_t)(j * 32));
                mma16(acc[0][2*j],   a[0], b[0], b[1]);
                mma16(acc[1][2*j],   a[1], b[0], b[1]);
                mma16(acc[0][2*j+1], a[0], b[2], b[3]);
                mma16(acc[1][2*j+1], a[1], b[2], b[3]);
            }
        }

        if (stage) sts_x(xbuf + ((gc + 2) & 3) * XBUFW);

        // per-tile epilogue (overlaps STS completion / barrier)
        if ((gc & 3) == 3){
            int tile = bid + (gc >> 2) * NSM;
#pragma unroll
            for (int mt = 0; mt < 2; ++mt){
#pragma unroll
                for (int rs = 0; rs < 2; ++rs){
                    int pos = tile * TILE_P + wp * 32 + mt * 16 + g + rs * 8;
                    int b = pos / HWSZ, p = pos - b * HWSZ;
                    float* ob = out + ((size_t)b * CHANS + (size_t)(wc * 64 + 2 * q)) * HWSZ + p;
#pragma unroll
                    for (int nt = 0; nt < 8; ++nt){
                        ob[(size_t)(nt * 8) * HWSZ]     = acc[mt][nt][rs * 2 + 0];
                        ob[(size_t)(nt * 8 + 1) * HWSZ] = acc[mt][nt][rs * 2 + 1];
                    }
                }
            }
#pragma unroll
            for (int mt = 0; mt < 2; ++mt)
#pragma unroll
                for (int nt = 0; nt < 8; ++nt)
#pragma unroll
                    for (int r = 0; r < 4; ++r) acc[mt][nt][r] = 0.f;
        }

        // barrier after odd chunks only (2 per tile)
        if ((gc & 1) == 1 && gc + 1 < gend) __syncthreads();
    }
}

// ---------------- launch ----------------
extern "C" void kernel_launch(void* const* d_in, const int* in_sizes, int n_in,
                              void* d_out, int out_size)
{
    const float* acts = (const float*)d_in[0];
    const float* wrec = (const float*)d_in[1];
    float* out        = (float*)d_out;
    (void)in_sizes; (void)n_in; (void)out_size;

    cudaFuncSetAttribute(gemm_kernel, cudaFuncAttributeMaxDynamicSharedMemorySize, SMEM_BYTES);

    build_weff_kernel<<<CHANS, CHANS>>>(wrec);
    gemm_kernel<<<NSM, 512, SMEM_BYTES>>>(acts, out);
}

// round 14
// speedup vs baseline: 1.1616x; 1.0785x over previous
#include <cuda_runtime.h>
#include <cuda_fp16.h>
#include <cstdint>
#include <cstddef>

#define CHANS 256
#define HWSZ  3136
#define BATCH 32
#define NPOS  (BATCH*HWSZ)        // 100352
#define STEPS 10
#define SCOPE 15
#define PADC  7

#define TILE_P 128                // positions per tile
#define KC     64                 // cin per chunk
#define NCHUNK (CHANS/KC)         // 4
#define NTILES (NPOS/TILE_P)      // 784
#define NSM    148                // persistent grid

// fp16 rows, strides in 4B words %32==4 -> ldmatrix 8-row tiles conflict-free
#define RSXW   68                 // X row: 128 pos fp16 = 64 words + 4 pad
#define RSWW   132                // W row: 256 cout fp16 = 128 words + 4 pad
#define XBUFW  (KC*RSXW)          // 4352 words per X buffer
#define WRESW  (256*RSWW)         // 33792 words resident W
#define XBUF_BYTES (XBUFW*4)      // 17408
#define SMEM_BYTES ((2*XBUFW + WRESW)*4)   // 169984 B

// W_eff = sum_{k=0..10} T^k, fp16: g_wh[cin][cout]
__device__ __half g_wh[CHANS*CHANS];

// ---------------- helpers ----------------
__device__ __forceinline__ uint32_t smem_u32(const void* p){
    uint32_t a;
    asm("{ .reg .u64 t; cvta.to.shared.u64 t, %1; cvt.u32.u64 %0, t; }" : "=r"(a) : "l"(p));
    return a;
}
__device__ __forceinline__ uint32_t pkh2(float hi, float lo){
    uint32_t r; asm("cvt.rn.f16x2.f32 %0, %1, %2;" : "=r"(r) : "f"(hi), "f"(lo)); return r;
}
__device__ __forceinline__ void ldmx4t(uint32_t* r, uint32_t addr){
    asm volatile("ldmatrix.sync.aligned.m8n8.x4.trans.shared.b16 {%0,%1,%2,%3}, [%4];"
        : "=r"(r[0]), "=r"(r[1]), "=r"(r[2]), "=r"(r[3]) : "r"(addr));
}
__device__ __forceinline__ void mma16(float* d, const uint32_t* a, uint32_t b0, uint32_t b1){
    asm volatile("mma.sync.aligned.m16n8k16.row.col.f32.f16.f16.f32 "
        "{%0,%1,%2,%3}, {%4,%5,%6,%7}, {%8,%9}, {%0,%1,%2,%3};"
        : "+f"(d[0]), "+f"(d[1]), "+f"(d[2]), "+f"(d[3])
        : "r"(a[0]), "r"(a[1]), "r"(a[2]), "r"(a[3]), "r"(b0), "r"(b1));
}

// ---------------- Kernel 1: build W_eff (fp16) ----------------
// Block j: column j of S = sum_{k=0..STEPS} T^k via S_{s+1} = I + T*S_s (exact,
// includes zero-pad boundaries). Thread i holds S[i][j] = W[cout=i][cin=j];
// writes g_wh[cin=j][cout=i].
__global__ void build_weff_kernel(const float* __restrict__ w){
    __shared__ float sv[CHANS + 2*PADC];
    const int i = threadIdx.x, j = blockIdx.x;
    if (i < PADC){ sv[i] = 0.f; sv[CHANS + PADC + i] = 0.f; }
    float wv[SCOPE];
#pragma unroll
    for (int k = 0; k < SCOPE; ++k) wv[k] = w[k];
    float v = (i == j) ? 1.f : 0.f;
    for (int s = 0; s < STEPS; ++s){
        __syncthreads();
        sv[PADC + i] = v;
        __syncthreads();
        float acc = (i == j) ? 1.f : 0.f;
#pragma unroll
        for (int k = 0; k < SCOPE; ++k) acc = fmaf(wv[k], sv[i + k], acc);
        v = acc;
    }
    g_wh[j * CHANS + i] = __float2half_rn(v);
}

// ---------------- Kernel 2: persistent GEMM out = W_eff * X ----------------
// 148 persistent CTAs, 256 threads, 8 warps of 64pos x 64cout tiles
// (acc = 128 regs; 1.0 ldmatrix-tile per MMA vs 1.5 at 32x64).
// W fully resident; X double-buffered KC=64 chunks, R11 schedule:
// LDG(gc+1) at top, STS at bottom, one barrier per chunk.
__global__ void __launch_bounds__(256, 1)
gemm_kernel(const float* __restrict__ x, float* __restrict__ out){
    extern __shared__ uint32_t smu[];
    uint32_t* xbuf = smu;              // 2 x [64][RSXW]
    uint32_t* wres = smu + 2*XBUFW;    // [256][RSWW]

    const int tid  = threadIdx.x;
    const int lane = tid & 31;
    const int wid  = tid >> 5;
    const int g = lane >> 2, q = lane & 3;
    const int wp = wid >> 2, wc = wid & 3;   // wp 0..1 (64 pos), wc 0..3 (64 cout)
    const int bid = blockIdx.x;

    // ---- one-time W load: plain copy g_wh rows -> [k][cout] fp16 ----
#pragma unroll
    for (int i = 0; i < 32; ++i){
        int id  = tid + i * 256;           // 0..8191
        int row = id >> 5;                 // 0..255 (cin)
        int c8  = (id & 31) << 3;          // cout group of 8
        const uint4 v = *(const uint4*)(g_wh + (size_t)row * CHANS + c8);
        *(uint4*)(wres + row * RSWW + (c8 >> 1)) = v;
    }

    const int ntiles = (NTILES - bid + NSM - 1) / NSM;   // 5 or 6
    const int gend   = ntiles * NCHUNK;                  // 20 or 24

    // X staging: thread -> k rows sk2+{0,16,32,48}, 8 consecutive pos
    const int sk2 = tid >> 4;              // 0..15
    const int sp8 = (tid & 15) << 3;       // 0..120  (8|3136 -> no straddle)

    float4 xf[8];
    auto ldg_x = [&](int gc){
        int t = gc >> 2, c = gc & 3;
        int tile = bid + t * NSM;
        int sn = tile * TILE_P + sp8;
        int b = sn / HWSZ, p = sn - b * HWSZ;
        const float* s = x + ((size_t)b * CHANS + (size_t)(c * KC + sk2)) * HWSZ + p;
#pragma unroll
        for (int rr = 0; rr < 4; ++rr){
            xf[2*rr]   = *(const float4*)(s + (size_t)(16*rr) * HWSZ);
            xf[2*rr+1] = *(const float4*)(s + (size_t)(16*rr) * HWSZ + 4);
        }
    };
    auto sts_x = [&](uint32_t* buf){
#pragma unroll
        for (int rr = 0; rr < 4; ++rr){
            uint4 v;
            v.x = pkh2(xf[2*rr].y,   xf[2*rr].x);
            v.y = pkh2(xf[2*rr].w,   xf[2*rr].z);
            v.z = pkh2(xf[2*rr+1].y, xf[2*rr+1].x);
            v.w = pkh2(xf[2*rr+1].w, xf[2*rr+1].z);
            *(uint4*)(buf + (sk2 + 16*rr) * RSXW + (sp8 >> 1)) = v;
        }
    };

    // ldmatrix per-lane base addresses (bytes)
    const int a_k = (lane & 7) + ((lane >> 4) << 3);        // A: lanes 16-31 -> +8 k
    const int a_p = ((lane >> 3) & 1) << 3;                 // A: lanes 8-15,24-31 -> +8 pos
    const uint32_t xaddr0 = smem_u32(xbuf) + (uint32_t)(a_k * (RSXW*4) + (wp * 64 + a_p) * 2);
    const int b_k = (lane & 7) + (((lane >> 3) & 1) << 3);  // B: lanes 8-15,24-31 -> +8 k
    const int b_c = ((lane >> 4) << 3);                     // B: lanes 16-31 -> +8 cout
    const uint32_t waddr0 = smem_u32(wres) + (uint32_t)(b_k * (RSWW*4) + (wc * 64 + b_c) * 2);

    float acc[4][8][4];
#pragma unroll
    for (int mt = 0; mt < 4; ++mt)
#pragma unroll
        for (int nt = 0; nt < 8; ++nt)
#pragma unroll
            for (int r = 0; r < 4; ++r) acc[mt][nt][r] = 0.f;

    // prologue: chunk0 into smem
    ldg_x(0);
    sts_x(xbuf);
    __syncthreads();   // covers resident W + buf0

    for (int gc = 0; gc < gend; ++gc){
        const bool more = (gc + 1 < gend);
        if (more) ldg_x(gc + 1);           // full chunk of compute cover

        const uint32_t xa_c = xaddr0 + (uint32_t)((gc & 1) * XBUF_BYTES);
        const uint32_t wa_c = waddr0 + (uint32_t)((gc & 3) * KC * (RSWW*4));
#pragma unroll
        for (int ks = 0; ks < 4; ++ks){
            const uint32_t xa_k = xa_c + (uint32_t)(ks * 16 * (RSXW*4));
            const uint32_t wa_k = wa_c + (uint32_t)(ks * 16 * (RSWW*4));
            uint32_t a[4][4];
#pragma unroll
            for (int mt = 0; mt < 4; ++mt)
                ldmx4t(a[mt], xa_k + (uint32_t)(mt * 32));   // pos wp*64 + mt*16
#pragma unroll
            for (int j = 0; j < 4; ++j){
                uint32_t b[4];
                ldmx4t(b, wa_k + (uint32_t)(j * 32));
#pragma unroll
                for (int mt = 0; mt < 4; ++mt){
                    mma16(acc[mt][2*j],   a[mt], b[0], b[1]);
                    mma16(acc[mt][2*j+1], a[mt], b[2], b[3]);
                }
            }
        }

        // STS at bottom (single-sync safety: buffer (gc+1)&1 last read at gc-1,
        // fenced by the barrier at end of gc-1)
        if (more) sts_x(xbuf + ((gc + 1) & 1) * XBUFW);

        // per-tile epilogue (overlaps STS completion / barrier)
        if ((gc & 3) == 3){
            int tile = bid + (gc >> 2) * NSM;
#pragma unroll
            for (int mt = 0; mt < 4; ++mt){
#pragma unroll
                for (int rs = 0; rs < 2; ++rs){
                    int pos = tile * TILE_P + wp * 64 + mt * 16 + g + rs * 8;
                    int b = pos / HWSZ, p = pos - b * HWSZ;
                    float* ob = out + ((size_t)b * CHANS + (size_t)(wc * 64 + 2 * q)) * HWSZ + p;
#pragma unroll
                    for (int nt = 0; nt < 8; ++nt){
                        ob[(size_t)(nt * 8) * HWSZ]     = acc[mt][nt][rs * 2 + 0];
                        ob[(size_t)(nt * 8 + 1) * HWSZ] = acc[mt][nt][rs * 2 + 1];
                    }
                }
            }
#pragma unroll
            for (int mt = 0; mt < 4; ++mt)
#pragma unroll
                for (int nt = 0; nt < 8; ++nt)
#pragma unroll
                    for (int r = 0; r < 4; ++r) acc[mt][nt][r] = 0.f;
        }

        if (more) __syncthreads();
    }
}

// ---------------- launch ----------------
extern "C" void kernel_launch(void* const* d_in, const int* in_sizes, int n_in,
                              void* d_out, int out_size)
{
    const float* acts = (const float*)d_in[0];
    const float* wrec = (const float*)d_in[1];
    float* out        = (float*)d_out;
    (void)in_sizes; (void)n_in; (void)out_size;

    cudaFuncSetAttribute(gemm_kernel, cudaFuncAttributeMaxDynamicSharedMemorySize, SMEM_BYTES);

    build_weff_kernel<<<CHANS, CHANS>>>(wrec);
    gemm_kernel<<<NSM, 256, SMEM_BYTES>>>(acts, out);
}